// round 1
// baseline (speedup 1.0000x reference)
#include <cuda_runtime.h>
#include <math.h>

#define Nn 2048
#define Dd 512
#define Hh 8
#define Ff 2048
#define EDd 64
#define Pp 4
#define Ee 32768

// ---------------- static scratch (no allocations allowed) ----------------
__device__ float g_xln[Nn * Dd];         // 4 MB
__device__ float g_Q[Hh * Nn * Dd];      // 32 MB
__device__ float g_K[Hh * Nn * Dd];      // 32 MB
__device__ float g_V[Hh * Nn * Dd];      // 32 MB
__device__ float g_d[Hh * Ee * Pp];      // 4 MB
__device__ float g_S[(long)Nn * Nn];     // 16 MB
__device__ float g_mh[(long)Nn * Hh * Dd]; // 32 MB
__device__ float g_x1[Nn * Dd];          // 4 MB
__device__ float g_h2[Nn * Dd];          // 4 MB
__device__ float g_ff[(long)Nn * Ff];    // 16 MB

// ---------------- layernorm: one block (128 thr) per row of 512 ----------------
__global__ void layernorm512(const float* __restrict__ x, const float* __restrict__ g,
                             const float* __restrict__ beta, float* __restrict__ out) {
    int row = blockIdx.x;
    const float* xr = x + (long)row * Dd;
    float* orow = out + (long)row * Dd;
    int tid = threadIdx.x;  // 128
    float v[4];
    float s = 0.f;
#pragma unroll
    for (int i = 0; i < 4; i++) { v[i] = xr[tid + i * 128]; s += v[i]; }
    __shared__ float red[4];
#pragma unroll
    for (int o = 16; o; o >>= 1) s += __shfl_xor_sync(0xffffffffu, s, o);
    if ((tid & 31) == 0) red[tid >> 5] = s;
    __syncthreads();
    float mu = (red[0] + red[1] + red[2] + red[3]) * (1.f / 512.f);
    float vs = 0.f;
#pragma unroll
    for (int i = 0; i < 4; i++) { float t = v[i] - mu; vs += t * t; }
#pragma unroll
    for (int o = 16; o; o >>= 1) vs += __shfl_xor_sync(0xffffffffu, vs, o);
    __syncthreads();
    if ((tid & 31) == 0) red[tid >> 5] = vs;
    __syncthreads();
    float var = (red[0] + red[1] + red[2] + red[3]) * (1.f / 512.f);
    float rstd = rsqrtf(var + 1e-5f);
#pragma unroll
    for (int i = 0; i < 4; i++) {
        int c = tid + i * 128;
        orow[c] = (v[i] - mu) * rstd * g[c] + beta[c];
    }
}

// ---------------- edge dot: d[h,e,p] = edge_attr[e,:] . edge_vec[h,p,:] ----------------
// block = 128 threads handles 4 edges x 32 (h,p)
__global__ void edge_d_kernel(const float* __restrict__ edge_attr,
                              const float* __restrict__ edge_vec,
                              float* __restrict__ dout) {
    __shared__ float ea[4][EDd];
    int e0 = blockIdx.x * 4;
    int tid = threadIdx.x;
    for (int i = tid; i < 4 * EDd; i += 128)
        ea[i >> 6][i & 63] = edge_attr[(long)e0 * EDd + i];
    __syncthreads();
    int el = tid >> 5;       // 0..3
    int hp = tid & 31;       // h*4+p
    const float* ev = edge_vec + hp * EDd;
    float s = 0.f;
#pragma unroll
    for (int f = 0; f < EDd; f++) s += ea[el][f] * ev[f];
    int h = hp >> 2, p = hp & 3;
    dout[((long)h * Ee + (e0 + el)) * Pp + p] = s;
}

// ---------------- per-head spatial/path bias add: S += b + c_h ----------------
__global__ void add_bias_c(float* __restrict__ S, const float* __restrict__ b,
                           const int* __restrict__ path_idx,
                           const int* __restrict__ path_len,
                           const float* __restrict__ dh) {
    long idx = (long)blockIdx.x * blockDim.x + threadIdx.x;
    int pl = path_len[idx];
    float c = 0.f;
    if (pl > 0) {
        const int4 pi = *reinterpret_cast<const int4*>(path_idx + idx * 4);
        float s = 0.f;
        if (0 < pl) s += dh[(long)pi.x * 4 + 0];
        if (1 < pl) s += dh[(long)pi.y * 4 + 1];
        if (2 < pl) s += dh[(long)pi.z * 4 + 2];
        if (3 < pl) s += dh[(long)pi.w * 4 + 3];
        c = s / (float)pl;
    }
    S[idx] += b[idx] + c;
}

// ---------------- row softmax over 2048, one block (256 thr) per row ----------------
__global__ void softmax2048(float* __restrict__ S) {
    int row = blockIdx.x;
    float* r = S + (long)row * Nn;
    int tid = threadIdx.x;  // 256
    float v[8];
    float m = -1e30f;
#pragma unroll
    for (int i = 0; i < 8; i++) { v[i] = r[tid + i * 256]; m = fmaxf(m, v[i]); }
    __shared__ float red[8];
#pragma unroll
    for (int o = 16; o; o >>= 1) m = fmaxf(m, __shfl_xor_sync(0xffffffffu, m, o));
    if ((tid & 31) == 0) red[tid >> 5] = m;
    __syncthreads();
    m = red[0];
#pragma unroll
    for (int i = 1; i < 8; i++) m = fmaxf(m, red[i]);
    float s = 0.f;
#pragma unroll
    for (int i = 0; i < 8; i++) { v[i] = __expf(v[i] - m); s += v[i]; }
#pragma unroll
    for (int o = 16; o; o >>= 1) s += __shfl_xor_sync(0xffffffffu, s, o);
    __syncthreads();
    if ((tid & 31) == 0) red[tid >> 5] = s;
    __syncthreads();
    s = red[0];
#pragma unroll
    for (int i = 1; i < 8; i++) s += red[i];
    float inv = 1.f / s;
#pragma unroll
    for (int i = 0; i < 8; i++) r[tid + i * 256] = v[i] * inv;
}

// ---------------- generic tiled SGEMM: C = alpha*A@op(B) + bias, epilogues ----------------
// NN: B is [K, Nc] with ldb;  NT: B is [Nc, K] with ldb (computes A@B^T)
// epi: 0 = none, 1 = gelu(exact), 2 = + resid[m*ldc+n]
template <bool NT>
__global__ void gemm_kernel(const float* __restrict__ A, const float* __restrict__ B,
                            const float* __restrict__ bias, const float* __restrict__ resid,
                            float* __restrict__ C, int M, int Nc, int K,
                            long strideA, long strideB, long strideBias, long strideC,
                            int ldb, int ldc, float alpha, int epi) {
    int bz = blockIdx.z;
    const float* Ab = A + (long)bz * strideA;
    const float* Bb = B + (long)bz * strideB;
    const float* biasb = bias ? bias + (long)bz * strideBias : nullptr;
    float* Cb = C + (long)bz * strideC;

    int m0 = blockIdx.y * 64;
    int n0 = blockIdx.x * 64;
    __shared__ float As[16][64];
    __shared__ float Bs[16][64];
    float acc[4][4];
#pragma unroll
    for (int i = 0; i < 4; i++)
#pragma unroll
        for (int j = 0; j < 4; j++) acc[i][j] = 0.f;

    int tid = threadIdx.x;
    int tx = tid & 15, ty = tid >> 4;

    for (int k0 = 0; k0 < K; k0 += 16) {
#pragma unroll
        for (int i = 0; i < 4; i++) {
            int idx = tid + i * 256;
            int r = idx >> 4, c = idx & 15;
            As[c][r] = Ab[(long)(m0 + r) * K + k0 + c];
        }
        if (!NT) {
#pragma unroll
            for (int i = 0; i < 4; i++) {
                int idx = tid + i * 256;
                int r = idx >> 6, c = idx & 63;
                Bs[r][c] = Bb[(long)(k0 + r) * ldb + n0 + c];
            }
        } else {
#pragma unroll
            for (int i = 0; i < 4; i++) {
                int idx = tid + i * 256;
                int nn = idx >> 4, kk = idx & 15;
                Bs[kk][nn] = Bb[(long)(n0 + nn) * ldb + k0 + kk];
            }
        }
        __syncthreads();
#pragma unroll
        for (int k = 0; k < 16; k++) {
            float a[4], bv[4];
#pragma unroll
            for (int i = 0; i < 4; i++) a[i] = As[k][ty * 4 + i];
#pragma unroll
            for (int j = 0; j < 4; j++) bv[j] = Bs[k][tx * 4 + j];
#pragma unroll
            for (int i = 0; i < 4; i++)
#pragma unroll
                for (int j = 0; j < 4; j++) acc[i][j] += a[i] * bv[j];
        }
        __syncthreads();
    }

#pragma unroll
    for (int i = 0; i < 4; i++) {
        int m = m0 + ty * 4 + i;
#pragma unroll
        for (int j = 0; j < 4; j++) {
            int n = n0 + tx * 4 + j;
            float vv = acc[i][j] * alpha;
            if (biasb) vv += biasb[n];
            if (epi == 1) {
                vv = 0.5f * vv * (1.0f + erff(vv * 0.70710678118654752f));
            } else if (epi == 2) {
                vv += resid[(long)m * ldc + n];
            }
            Cb[(long)m * ldc + n] = vv;
        }
    }
}

static inline void launch_gemm_nn(const float* A, const float* B, const float* bias,
                                  const float* resid, float* C, int M, int Nc, int K,
                                  long sA, long sB, long sBias, long sC, int batch,
                                  int ldb, int ldc, float alpha, int epi) {
    dim3 grid(Nc / 64, M / 64, batch);
    gemm_kernel<false><<<grid, 256>>>(A, B, bias, resid, C, M, Nc, K, sA, sB, sBias, sC,
                                      ldb, ldc, alpha, epi);
}
static inline void launch_gemm_nt(const float* A, const float* B, float* C,
                                  int M, int Nc, int K, int ldb, int ldc, float alpha) {
    dim3 grid(Nc / 64, M / 64, 1);
    gemm_kernel<true><<<grid, 256>>>(A, B, nullptr, nullptr, C, M, Nc, K, 0, 0, 0, 0,
                                     ldb, ldc, alpha, 0);
}

extern "C" void kernel_launch(void* const* d_in, const int* in_sizes, int n_in,
                              void* d_out, int out_size) {
    const float* x         = (const float*)d_in[0];
    const float* edge_attr = (const float*)d_in[1];
    const float* b         = (const float*)d_in[2];
    const int*   path_idx  = (const int*)d_in[3];
    const int*   path_len  = (const int*)d_in[4];
    const float* Wq        = (const float*)d_in[5];
    const float* bq        = (const float*)d_in[6];
    const float* Wk        = (const float*)d_in[7];
    const float* bk        = (const float*)d_in[8];
    const float* Wv        = (const float*)d_in[9];
    const float* bv        = (const float*)d_in[10];
    const float* edge_vec  = (const float*)d_in[11];
    const float* Wo        = (const float*)d_in[12];
    const float* bo        = (const float*)d_in[13];
    const float* ln1_g     = (const float*)d_in[14];
    const float* ln1_b     = (const float*)d_in[15];
    const float* ln2_g     = (const float*)d_in[16];
    const float* ln2_b     = (const float*)d_in[17];
    const float* W1        = (const float*)d_in[18];
    const float* b1        = (const float*)d_in[19];
    const float* W2        = (const float*)d_in[20];
    const float* b2        = (const float*)d_in[21];
    float* out = (float*)d_out;

    float *xln, *Q, *K, *V, *dmat, *S, *mh, *x1, *h2, *ff;
    cudaGetSymbolAddress((void**)&xln, g_xln);
    cudaGetSymbolAddress((void**)&Q, g_Q);
    cudaGetSymbolAddress((void**)&K, g_K);
    cudaGetSymbolAddress((void**)&V, g_V);
    cudaGetSymbolAddress((void**)&dmat, g_d);
    cudaGetSymbolAddress((void**)&S, g_S);
    cudaGetSymbolAddress((void**)&mh, g_mh);
    cudaGetSymbolAddress((void**)&x1, g_x1);
    cudaGetSymbolAddress((void**)&h2, g_h2);
    cudaGetSymbolAddress((void**)&ff, g_ff);

    const float scale = 1.0f / sqrtf((float)Dd);

    // 1) LN1
    layernorm512<<<Nn, 128>>>(x, ln1_g, ln1_b, xln);

    // 2) edge dot products d[h,e,p]
    edge_d_kernel<<<Ee / 4, 128>>>(edge_attr, edge_vec, dmat);

    // 3) Q/K/V projections (batched over heads)
    launch_gemm_nn(xln, Wq, bq, nullptr, Q, Nn, Dd, Dd, 0, (long)Dd * Dd, Dd,
                   (long)Nn * Dd, Hh, Dd, Dd, 1.0f, 0);
    launch_gemm_nn(xln, Wk, bk, nullptr, K, Nn, Dd, Dd, 0, (long)Dd * Dd, Dd,
                   (long)Nn * Dd, Hh, Dd, Dd, 1.0f, 0);
    launch_gemm_nn(xln, Wv, bv, nullptr, V, Nn, Dd, Dd, 0, (long)Dd * Dd, Dd,
                   (long)Nn * Dd, Hh, Dd, Dd, 1.0f, 0);

    // 4) per-head attention through one [N,N] scratch
    for (int h = 0; h < Hh; h++) {
        const float* Qh = Q + (long)h * Nn * Dd;
        const float* Kh = K + (long)h * Nn * Dd;
        const float* Vh = V + (long)h * Nn * Dd;
        // S = scale * Qh @ Kh^T
        launch_gemm_nt(Qh, Kh, S, Nn, Nn, Dd, Dd, Nn, scale);
        // S += b + c_h
        add_bias_c<<<(Nn * (long)Nn) / 256, 256>>>(S, b, path_idx, path_len,
                                                   dmat + (long)h * Ee * Pp);
        // softmax rows
        softmax2048<<<Nn, 256>>>(S);
        // mh[:, h*D:(h+1)*D] = S @ Vh
        launch_gemm_nn(S, Vh, nullptr, nullptr, mh + (long)h * Dd, Nn, Dd, Nn,
                       0, 0, 0, 0, 1, Dd, Hh * Dd, 1.0f, 0);
    }

    // 5) output projection + residual: x1 = mh @ Wo + bo + x
    launch_gemm_nn(mh, Wo, bo, x, x1, Nn, Dd, Hh * Dd, 0, 0, 0, 0, 1,
                   Dd, Dd, 1.0f, 2);

    // 6) LN2
    layernorm512<<<Nn, 128>>>(x1, ln2_g, ln2_b, h2);

    // 7) FF: ff = gelu(h2 @ W1 + b1); out = ff @ W2 + b2 + x1
    launch_gemm_nn(h2, W1, b1, nullptr, ff, Nn, Ff, Dd, 0, 0, 0, 0, 1,
                   Ff, Ff, 1.0f, 1);
    launch_gemm_nn(ff, W2, b2, x1, out, Nn, Dd, Ff, 0, 0, 0, 0, 1,
                   Dd, Dd, 1.0f, 2);
}

// round 2
// speedup vs baseline: 1.7031x; 1.7031x over previous
#include <cuda_runtime.h>
#include <mma.h>
#include <math.h>
#include <type_traits>

using namespace nvcuda;

#define Nn 2048
#define Dd 512
#define Hh 8
#define Ff 2048
#define EDd 64
#define Pp 4
#define Ee 32768

// ---------------- static scratch (no allocations allowed) ----------------
__device__ float g_xln[Nn * Dd];               // 4 MB  (also reused as GEMM tmp later)
__device__ float g_Q[Hh * Nn * Dd];            // 32 MB
__device__ float g_K[Hh * Nn * Dd];            // 32 MB
__device__ float g_V[Hh * Nn * Dd];            // 32 MB
__device__ float g_d[Hh * Ee * Pp];            // 4 MB
__device__ float g_S[(long)Hh * Nn * Nn];      // 128 MB (all heads)
__device__ float g_mh[(long)Nn * Hh * Dd];     // 32 MB
__device__ float g_x1[Nn * Dd];                // 4 MB
__device__ float g_h2[Nn * Dd];                // 4 MB
__device__ float g_ff[(long)Nn * Ff];          // 16 MB

// ---------------- layernorm: one block (128 thr) per row of 512 ----------------
__global__ void layernorm512(const float* __restrict__ x, const float* __restrict__ g,
                             const float* __restrict__ beta, float* __restrict__ out) {
    int row = blockIdx.x;
    const float* xr = x + (long)row * Dd;
    float* orow = out + (long)row * Dd;
    int tid = threadIdx.x;  // 128
    float v[4];
    float s = 0.f;
#pragma unroll
    for (int i = 0; i < 4; i++) { v[i] = xr[tid + i * 128]; s += v[i]; }
    __shared__ float red[4];
#pragma unroll
    for (int o = 16; o; o >>= 1) s += __shfl_xor_sync(0xffffffffu, s, o);
    if ((tid & 31) == 0) red[tid >> 5] = s;
    __syncthreads();
    float mu = (red[0] + red[1] + red[2] + red[3]) * (1.f / 512.f);
    float vs = 0.f;
#pragma unroll
    for (int i = 0; i < 4; i++) { float t = v[i] - mu; vs += t * t; }
#pragma unroll
    for (int o = 16; o; o >>= 1) vs += __shfl_xor_sync(0xffffffffu, vs, o);
    __syncthreads();
    if ((tid & 31) == 0) red[tid >> 5] = vs;
    __syncthreads();
    float var = (red[0] + red[1] + red[2] + red[3]) * (1.f / 512.f);
    float rstd = rsqrtf(var + 1e-5f);
#pragma unroll
    for (int i = 0; i < 4; i++) {
        int c = tid + i * 128;
        orow[c] = (v[i] - mu) * rstd * g[c] + beta[c];
    }
}

// ---------------- edge dot: d[h,e,p] = edge_attr[e,:] . edge_vec[h,p,:] ----------------
__global__ void edge_d_kernel(const float* __restrict__ edge_attr,
                              const float* __restrict__ edge_vec,
                              float* __restrict__ dout) {
    __shared__ float ea[4][EDd];
    int e0 = blockIdx.x * 4;
    int tid = threadIdx.x;
    for (int i = tid; i < 4 * EDd; i += 128)
        ea[i >> 6][i & 63] = edge_attr[(long)e0 * EDd + i];
    __syncthreads();
    int el = tid >> 5;       // 0..3
    int hp = tid & 31;       // h*4+p
    const float* ev = edge_vec + hp * EDd;
    float s = 0.f;
#pragma unroll
    for (int f = 0; f < EDd; f++) s += ea[el][f] * ev[f];
    int h = hp >> 2, p = hp & 3;
    dout[((long)h * Ee + (e0 + el)) * Pp + p] = s;
}

// ---------------- fused bias(b) + path-bias(c) + softmax, per (h,row) ----------------
// grid = (Hh, Nn): h fastest so 8 head-blocks of the same row run together (L2 reuse of path data)
__global__ void bias_c_softmax(float* __restrict__ S, const float* __restrict__ b,
                               const int* __restrict__ path_idx,
                               const int* __restrict__ path_len,
                               const float* __restrict__ dmat) {
    int h = blockIdx.x;
    int row = blockIdx.y;
    float* r = S + ((long)h * Nn + row) * Nn;
    const float* br = b + (long)row * Nn;
    const int* plr = path_len + (long)row * Nn;
    const int* pir = path_idx + (long)row * Nn * Pp;
    const float* dh = dmat + (long)h * Ee * Pp;
    int tid = threadIdx.x;  // 256
    float v[8];
    float m = -1e30f;
#pragma unroll
    for (int i = 0; i < 8; i++) {
        int col = tid + i * 256;
        int pl = plr[col];
        float c = 0.f;
        if (pl > 0) {
            const int4 pi = *reinterpret_cast<const int4*>(pir + (long)col * 4);
            float s = dh[(long)pi.x * 4 + 0];
            if (1 < pl) s += dh[(long)pi.y * 4 + 1];
            if (2 < pl) s += dh[(long)pi.z * 4 + 2];
            if (3 < pl) s += dh[(long)pi.w * 4 + 3];
            c = s / (float)pl;
        }
        v[i] = r[col] + br[col] + c;
        m = fmaxf(m, v[i]);
    }
    __shared__ float red[8];
#pragma unroll
    for (int o = 16; o; o >>= 1) m = fmaxf(m, __shfl_xor_sync(0xffffffffu, m, o));
    if ((tid & 31) == 0) red[tid >> 5] = m;
    __syncthreads();
    m = red[0];
#pragma unroll
    for (int i = 1; i < 8; i++) m = fmaxf(m, red[i]);
    float s = 0.f;
#pragma unroll
    for (int i = 0; i < 8; i++) { v[i] = __expf(v[i] - m); s += v[i]; }
#pragma unroll
    for (int o = 16; o; o >>= 1) s += __shfl_xor_sync(0xffffffffu, s, o);
    __syncthreads();
    if ((tid & 31) == 0) red[tid >> 5] = s;
    __syncthreads();
    s = red[0];
#pragma unroll
    for (int i = 1; i < 8; i++) s += red[i];
    float inv = 1.f / s;
#pragma unroll
    for (int i = 0; i < 8; i++) r[tid + i * 256] = v[i] * inv;
}

// ---------------- elementwise epilogues ----------------
__global__ void bias_scale(float* __restrict__ X, const float* __restrict__ bias,
                           float scale) {
    long h = blockIdx.y;
    long i = (long)blockIdx.x * 256 + threadIdx.x;
    float* Xb = X + h * (long)Nn * Dd;
    const float* bb = bias + h * Dd;
    Xb[i] = (Xb[i] + bb[i & (Dd - 1)]) * scale;
}

__global__ void bias_resid(float* __restrict__ out, const float* __restrict__ Cin,
                           const float* __restrict__ bias, const float* __restrict__ resid,
                           int mask) {
    long i = (long)blockIdx.x * 256 + threadIdx.x;
    out[i] = Cin[i] + bias[i & mask] + resid[i];
}

__global__ void bias_gelu(float* __restrict__ X, const float* __restrict__ bias,
                          int mask) {
    long i = (long)blockIdx.x * 256 + threadIdx.x;
    float vv = X[i] + bias[i & mask];
    X[i] = 0.5f * vv * (1.0f + erff(vv * 0.70710678118654752f));
}

// ---------------- wmma TF32 GEMM: C = A @ op(B) ----------------
// A row-major [M,K] (lda=K). NN: B row-major [K,Nc] ldb. NT: B row-major [Nc,K] ldb (C=A@B^T).
// SPLIT==1: plain tf32 (1 mma). SPLIT==3: 3xTF32 split (hi/lo, ~fp32 accuracy).
template <bool NT, int SPLIT>
__launch_bounds__(256)
__global__ void wmma_gemm(const float* __restrict__ A, const float* __restrict__ B,
                          float* __restrict__ C, int M, int Nc, int K,
                          long sA, long sB, long sC, int ldb, int ldc) {
    constexpr int BM = 128, BN = 128, BK = 16;
    constexpr int AP = 16;                 // As pitch (floats)
    constexpr int BPITCH = NT ? 16 : 136;  // Bs pitch
    constexpr int BROWS  = NT ? 128 : 16;

    __shared__ __align__(32) float As[2][BM][AP];
    __shared__ __align__(32) float Bs[2][BROWS][BPITCH];

    int bz = blockIdx.z;
    const float* Ab = A + (long)bz * sA;
    const float* Bb = B + (long)bz * sB;
    float* Cb = C + (long)bz * sC;
    int m0 = blockIdx.y * BM;
    int n0 = blockIdx.x * BN;
    int tid = threadIdx.x;
    int warpId = tid >> 5;
    int wm = warpId & 3;   // 4 warps along M, 32 rows each
    int wn = warpId >> 2;  // 2 warps along N, 64 cols each

    wmma::fragment<wmma::accumulator, 16, 16, 8, float> acc[2][4];
#pragma unroll
    for (int i = 0; i < 2; i++)
#pragma unroll
        for (int j = 0; j < 4; j++) wmma::fill_fragment(acc[i][j], 0.0f);

    auto loadA = [&](int buf, int k0) {
#pragma unroll
        for (int it = 0; it < 2; it++) {
            int idx = tid + it * 256;
            int r = idx >> 2, c = (idx & 3) * 4;
            float4 t = *reinterpret_cast<const float4*>(&Ab[(long)(m0 + r) * K + k0 + c]);
            *reinterpret_cast<float4*>(&As[buf][r][c]) = t;
        }
    };
    auto loadB = [&](int buf, int k0) {
        if (!NT) {
#pragma unroll
            for (int it = 0; it < 2; it++) {
                int idx = tid + it * 256;
                int r = idx >> 5, c = (idx & 31) * 4;
                float4 t = *reinterpret_cast<const float4*>(&Bb[(long)(k0 + r) * ldb + n0 + c]);
                *reinterpret_cast<float4*>(&Bs[buf][r][c]) = t;
            }
        } else {
#pragma unroll
            for (int it = 0; it < 2; it++) {
                int idx = tid + it * 256;
                int r = idx >> 2, c = (idx & 3) * 4;
                float4 t = *reinterpret_cast<const float4*>(&Bb[(long)(n0 + r) * ldb + k0 + c]);
                *reinterpret_cast<float4*>(&Bs[buf][r][c]) = t;
            }
        }
    };

    loadA(0, 0);
    loadB(0, 0);
    __syncthreads();

    typedef typename std::conditional<NT, wmma::col_major, wmma::row_major>::type BLay;

    int nk = K / BK;
    for (int kt = 0; kt < nk; kt++) {
        int buf = kt & 1;
        if (kt + 1 < nk) {
            loadA(buf ^ 1, (kt + 1) * BK);
            loadB(buf ^ 1, (kt + 1) * BK);
        }
#pragma unroll
        for (int kk = 0; kk < BK; kk += 8) {
            wmma::fragment<wmma::matrix_a, 16, 16, 8, wmma::precision::tf32, wmma::row_major> a_hi[2], a_lo[2];
            wmma::fragment<wmma::matrix_b, 16, 16, 8, wmma::precision::tf32, BLay> b_hi[4], b_lo[4];
#pragma unroll
            for (int i = 0; i < 2; i++) {
                wmma::load_matrix_sync(a_hi[i], &As[buf][wm * 32 + i * 16][kk], AP);
                if (SPLIT == 3) {
#pragma unroll
                    for (int t = 0; t < a_hi[i].num_elements; t++) {
                        float v = a_hi[i].x[t];
                        float hpart = wmma::__float_to_tf32(v);
                        a_hi[i].x[t] = hpart;
                        a_lo[i].x[t] = wmma::__float_to_tf32(v - hpart);
                    }
                } else {
#pragma unroll
                    for (int t = 0; t < a_hi[i].num_elements; t++)
                        a_hi[i].x[t] = wmma::__float_to_tf32(a_hi[i].x[t]);
                }
            }
#pragma unroll
            for (int j = 0; j < 4; j++) {
                const float* bp = NT ? &Bs[buf][wn * 64 + j * 16][kk]
                                     : &Bs[buf][kk][wn * 64 + j * 16];
                wmma::load_matrix_sync(b_hi[j], bp, BPITCH);
                if (SPLIT == 3) {
#pragma unroll
                    for (int t = 0; t < b_hi[j].num_elements; t++) {
                        float v = b_hi[j].x[t];
                        float hpart = wmma::__float_to_tf32(v);
                        b_hi[j].x[t] = hpart;
                        b_lo[j].x[t] = wmma::__float_to_tf32(v - hpart);
                    }
                } else {
#pragma unroll
                    for (int t = 0; t < b_hi[j].num_elements; t++)
                        b_hi[j].x[t] = wmma::__float_to_tf32(b_hi[j].x[t]);
                }
            }
#pragma unroll
            for (int i = 0; i < 2; i++)
#pragma unroll
                for (int j = 0; j < 4; j++) {
                    wmma::mma_sync(acc[i][j], a_hi[i], b_hi[j], acc[i][j]);
                    if (SPLIT == 3) {
                        wmma::mma_sync(acc[i][j], a_lo[i], b_hi[j], acc[i][j]);
                        wmma::mma_sync(acc[i][j], a_hi[i], b_lo[j], acc[i][j]);
                    }
                }
        }
        __syncthreads();
    }

#pragma unroll
    for (int i = 0; i < 2; i++)
#pragma unroll
        for (int j = 0; j < 4; j++) {
            float* cp = &Cb[(long)(m0 + wm * 32 + i * 16) * ldc + n0 + wn * 64 + j * 16];
            wmma::store_matrix_sync(cp, acc[i][j], ldc, wmma::mem_row_major);
        }
}

extern "C" void kernel_launch(void* const* d_in, const int* in_sizes, int n_in,
                              void* d_out, int out_size) {
    const float* x         = (const float*)d_in[0];
    const float* edge_attr = (const float*)d_in[1];
    const float* b         = (const float*)d_in[2];
    const int*   path_idx  = (const int*)d_in[3];
    const int*   path_len  = (const int*)d_in[4];
    const float* Wq        = (const float*)d_in[5];
    const float* bq        = (const float*)d_in[6];
    const float* Wk        = (const float*)d_in[7];
    const float* bk        = (const float*)d_in[8];
    const float* Wv        = (const float*)d_in[9];
    const float* bv        = (const float*)d_in[10];
    const float* edge_vec  = (const float*)d_in[11];
    const float* Wo        = (const float*)d_in[12];
    const float* bo        = (const float*)d_in[13];
    const float* ln1_g     = (const float*)d_in[14];
    const float* ln1_b     = (const float*)d_in[15];
    const float* ln2_g     = (const float*)d_in[16];
    const float* ln2_b     = (const float*)d_in[17];
    const float* W1        = (const float*)d_in[18];
    const float* b1        = (const float*)d_in[19];
    const float* W2        = (const float*)d_in[20];
    const float* b2        = (const float*)d_in[21];
    float* out = (float*)d_out;

    float *xln, *Q, *K, *V, *dmat, *S, *mh, *x1, *h2, *ff;
    cudaGetSymbolAddress((void**)&xln, g_xln);
    cudaGetSymbolAddress((void**)&Q, g_Q);
    cudaGetSymbolAddress((void**)&K, g_K);
    cudaGetSymbolAddress((void**)&V, g_V);
    cudaGetSymbolAddress((void**)&dmat, g_d);
    cudaGetSymbolAddress((void**)&S, g_S);
    cudaGetSymbolAddress((void**)&mh, g_mh);
    cudaGetSymbolAddress((void**)&x1, g_x1);
    cudaGetSymbolAddress((void**)&h2, g_h2);
    cudaGetSymbolAddress((void**)&ff, g_ff);

    const float scale = 1.0f / sqrtf((float)Dd);

    // 1) LN1
    layernorm512<<<Nn, 128>>>(x, ln1_g, ln1_b, xln);

    // 2) edge dot products d[h,e,p]
    edge_d_kernel<<<Ee / 4, 128>>>(edge_attr, edge_vec, dmat);

    // 3) Q/K/V projections, batched over heads (plain tf32)
    {
        dim3 g(Dd / 128, Nn / 128, Hh);
        wmma_gemm<false, 1><<<g, 256>>>(xln, Wq, Q, Nn, Dd, Dd, 0, (long)Dd * Dd,
                                        (long)Nn * Dd, Dd, Dd);
        wmma_gemm<false, 1><<<g, 256>>>(xln, Wk, K, Nn, Dd, Dd, 0, (long)Dd * Dd,
                                        (long)Nn * Dd, Dd, Dd);
        wmma_gemm<false, 1><<<g, 256>>>(xln, Wv, V, Nn, Dd, Dd, 0, (long)Dd * Dd,
                                        (long)Nn * Dd, Dd, Dd);
    }
    {
        dim3 g((Nn * Dd) / 256, Hh);
        bias_scale<<<g, 256>>>(Q, bq, scale);   // fold 1/sqrt(D) into Q
        bias_scale<<<g, 256>>>(K, bk, 1.0f);
        bias_scale<<<g, 256>>>(V, bv, 1.0f);
    }

    // 4) scores S[h] = Q[h] @ K[h]^T, all heads batched (plain tf32)
    {
        dim3 g(Nn / 128, Nn / 128, Hh);
        wmma_gemm<true, 1><<<g, 256>>>(Q, K, S, Nn, Nn, Dd, (long)Nn * Dd,
                                       (long)Nn * Dd, (long)Nn * Nn, Dd, Nn);
    }

    // 5) fused spatial-bias + path-bias + softmax
    bias_c_softmax<<<dim3(Hh, Nn), 256>>>(S, b, path_idx, path_len, dmat);

    // 6) mh[:, h*D:(h+1)*D] = S[h] @ V[h], batched (plain tf32)
    {
        dim3 g(Dd / 128, Nn / 128, Hh);
        wmma_gemm<false, 1><<<g, 256>>>(S, V, mh, Nn, Dd, Nn, (long)Nn * Nn,
                                        (long)Nn * Dd, Dd, Dd, Hh * Dd);
    }

    // 7) output projection (3xTF32) + residual: x1 = mh @ Wo + bo + x
    {
        dim3 g(Dd / 128, Nn / 128, 1);
        wmma_gemm<false, 3><<<g, 256>>>(mh, Wo, xln, Nn, Dd, Hh * Dd, 0, 0, 0, Dd, Dd);
        bias_resid<<<(Nn * Dd) / 256, 256>>>(x1, xln, bo, x, Dd - 1);
    }

    // 8) LN2
    layernorm512<<<Nn, 128>>>(x1, ln2_g, ln2_b, h2);

    // 9) FF (both 3xTF32): ff = gelu(h2 @ W1 + b1); out = ff @ W2 + b2 + x1
    {
        dim3 g1(Ff / 128, Nn / 128, 1);
        wmma_gemm<false, 3><<<g1, 256>>>(h2, W1, ff, Nn, Ff, Dd, 0, 0, 0, Ff, Ff);
        bias_gelu<<<((long)Nn * Ff) / 256, 256>>>(ff, b1, Ff - 1);
        dim3 g2(Dd / 128, Nn / 128, 1);
        wmma_gemm<false, 3><<<g2, 256>>>(ff, W2, xln, Nn, Dd, Ff, 0, 0, 0, Dd, Dd);
        bias_resid<<<(Nn * Dd) / 256, 256>>>(out, xln, b2, x1, Dd - 1);
    }
}

// round 4
// speedup vs baseline: 3.0709x; 1.8031x over previous
#include <cuda_runtime.h>
#include <cuda_bf16.h>
#include <math.h>
#include <stdint.h>

#define Nn 2048
#define Dd 512
#define Hh 8
#define Ff 2048
#define EDd 64
#define Pp 4
#define Ee 32768

typedef __nv_bfloat16 bf16;

// ---------------- static scratch (no allocations allowed) ----------------
__device__ float g_Q[Hh * Nn * Dd];             // 32 MB (also reused as GEMM tmp)
__device__ float g_K[Hh * Nn * Dd];             // 32 MB
__device__ float g_V[Hh * Nn * Dd];             // 32 MB
__device__ float g_S[(size_t)Hh * Nn * Nn];     // 128 MB (scores; FF1 tmp reuse)
__device__ float g_mh[(size_t)Nn * Hh * Dd];    // 32 MB
__device__ float g_x1[Nn * Dd];                 // 4 MB
__device__ float g_dmat[Hh * Ee * Pp];          // 4 MB

__device__ bf16 g_xh[Nn * Dd], g_xl[Nn * Dd];
__device__ bf16 g_Qh[Hh * Nn * Dd], g_Ql[Hh * Nn * Dd];
__device__ bf16 g_Kh[Hh * Nn * Dd], g_Kl[Hh * Nn * Dd];
__device__ bf16 g_Vth[Hh * Dd * Nn], g_Vtl[Hh * Dd * Nn];
__device__ bf16 g_Sh[(size_t)Hh * Nn * Nn], g_Sl[(size_t)Hh * Nn * Nn];  // 128 MB
__device__ bf16 g_mhh[(size_t)Nn * Hh * Dd], g_mhl[(size_t)Nn * Hh * Dd];
__device__ bf16 g_h2h[Nn * Dd], g_h2l[Nn * Dd];
__device__ bf16 g_ffh[Nn * Ff], g_ffl[Nn * Ff];
__device__ bf16 g_Wqh[Hh * Dd * Dd], g_Wql[Hh * Dd * Dd];
__device__ bf16 g_Wkh[Hh * Dd * Dd], g_Wkl[Hh * Dd * Dd];
__device__ bf16 g_Wvh[Hh * Dd * Dd], g_Wvl[Hh * Dd * Dd];
__device__ bf16 g_Woh[Dd * Hh * Dd], g_Wol[Dd * Hh * Dd];
__device__ bf16 g_W1h[Ff * Dd], g_W1l[Ff * Dd];
__device__ bf16 g_W2h[Dd * Ff], g_W2l[Dd * Ff];

// ---------------- low-level helpers ----------------
__device__ __forceinline__ uint32_t smem_u32(const void* p) {
    uint32_t a;
    asm("{ .reg .u64 t; cvta.to.shared.u64 t, %1; cvt.u32.u64 %0, t; }" : "=r"(a) : "l"(p));
    return a;
}
__device__ __forceinline__ void ldm4(uint32_t* r, uint32_t addr) {
    asm volatile("ldmatrix.sync.aligned.m8n8.x4.shared.b16 {%0,%1,%2,%3}, [%4];"
                 : "=r"(r[0]), "=r"(r[1]), "=r"(r[2]), "=r"(r[3]) : "r"(addr));
}
__device__ __forceinline__ void mma16816(float* d, const uint32_t* a, const uint32_t* b) {
    asm volatile(
        "mma.sync.aligned.m16n8k16.row.col.f32.bf16.bf16.f32 "
        "{%0,%1,%2,%3}, {%4,%5,%6,%7}, {%8,%9}, {%0,%1,%2,%3};"
        : "+f"(d[0]), "+f"(d[1]), "+f"(d[2]), "+f"(d[3])
        : "r"(a[0]), "r"(a[1]), "r"(a[2]), "r"(a[3]), "r"(b[0]), "r"(b[1]));
}
__device__ __forceinline__ void cp16(uint32_t sdst, const void* gsrc) {
    asm volatile("cp.async.cg.shared.global [%0], [%1], 16;" :: "r"(sdst), "l"(gsrc));
}
#define CP_COMMIT() asm volatile("cp.async.commit_group;" ::: "memory")
#define CP_WAIT(n)  asm volatile("cp.async.wait_group %0;" :: "n"(n) : "memory")

// SMEM stage layout (bf16, 80B row pitch for conflict-free ldmatrix)
#define STG   40960
#define OAH   0
#define OAL   10240
#define OBH   20480
#define OBL   30720
#define SMEM_GEMM (2 * STG)   // 81920

// load one 128x32 bf16 tile (row-major, leading dim ld) into pitched smem
__device__ __forceinline__ void cp_tile(uint32_t sdst, const bf16* __restrict__ src,
                                        int ld, int row0, int k0, int tid) {
#pragma unroll
    for (int it = 0; it < 2; it++) {
        int idx = tid + it * 256;
        int r = idx >> 2, c = idx & 3;
        cp16(sdst + r * 80 + c * 16, src + (size_t)(row0 + r) * ld + k0 + c * 8);
    }
}

// ---------------- split-bf16 mma.sync GEMM: C[M,N] = sum_k A[m,k]*B[n,k] ----------------
// A, B row-major K-major (hi+lo pairs). 3 passes: Ah*Bh + Al*Bh + Ah*Bl, fp32 accum.
__global__ void __launch_bounds__(256, 1)
mma_gemm(const bf16* __restrict__ Ah_, const bf16* __restrict__ Al_,
         const bf16* __restrict__ Bh_, const bf16* __restrict__ Bl_,
         float* __restrict__ C, int K, int lda, int ldb, int ldc,
         long sA, long sB, long sC) {
    extern __shared__ char smem[];
    const int tid = threadIdx.x;
    const int lane = tid & 31;
    const int wid = tid >> 5;
    const int wm = wid & 3;   // 4 warps along M (32 rows each)
    const int wn = wid >> 2;  // 2 warps along N (64 cols each)
    const int bz = blockIdx.z;
    const bf16* Ahb = Ah_ + (size_t)bz * sA;
    const bf16* Alb = Al_ + (size_t)bz * sA;
    const bf16* Bhb = Bh_ + (size_t)bz * sB;
    const bf16* Blb = Bl_ + (size_t)bz * sB;
    float* Cb = C + (size_t)bz * sC;
    const int m0 = blockIdx.y * 128;
    const int n0 = blockIdx.x * 128;
    const uint32_t sb = smem_u32(smem);

    float acc[2][8][4];
#pragma unroll
    for (int i = 0; i < 2; i++)
#pragma unroll
        for (int j = 0; j < 8; j++)
#pragma unroll
            for (int t = 0; t < 4; t++) acc[i][j][t] = 0.f;

    // ldmatrix lane address components
    const int rowA = (lane & 15);             // + mi*16 + wm*32
    const int colA = (lane >> 4) * 8;         // + ks*16
    const int rowB = (lane & 7) + ((lane >> 4) & 1) * 8;  // + nj16*16 + wn*64
    const int colB = ((lane >> 3) & 1) * 8;   // + ks*16

    const int nk = K >> 5;  // BK = 32

    // prologue
    {
        uint32_t s0 = sb;
        cp_tile(s0 + OAH, Ahb, lda, m0, 0, tid);
        cp_tile(s0 + OAL, Alb, lda, m0, 0, tid);
        cp_tile(s0 + OBH, Bhb, ldb, n0, 0, tid);
        cp_tile(s0 + OBL, Blb, ldb, n0, 0, tid);
        CP_COMMIT();
    }

    for (int kt = 0; kt < nk; kt++) {
        if (kt + 1 < nk) {
            uint32_t s1 = sb + ((kt + 1) & 1) * STG;
            int k0 = (kt + 1) << 5;
            cp_tile(s1 + OAH, Ahb, lda, m0, k0, tid);
            cp_tile(s1 + OAL, Alb, lda, m0, k0, tid);
            cp_tile(s1 + OBH, Bhb, ldb, n0, k0, tid);
            cp_tile(s1 + OBL, Blb, ldb, n0, k0, tid);
            CP_COMMIT();
            CP_WAIT(1);
        } else {
            CP_WAIT(0);
        }
        __syncthreads();

        uint32_t s0 = sb + (kt & 1) * STG;
#pragma unroll
        for (int ks = 0; ks < 2; ks++) {
            uint32_t ah[2][4], al[2][4], bh[4][4], bl[4][4];
#pragma unroll
            for (int mi = 0; mi < 2; mi++) {
                uint32_t off = (uint32_t)((wm * 32 + mi * 16 + rowA) * 80 +
                                          (ks * 16 + colA) * 2);
                ldm4(ah[mi], s0 + OAH + off);
                ldm4(al[mi], s0 + OAL + off);
            }
#pragma unroll
            for (int nj = 0; nj < 4; nj++) {
                uint32_t off = (uint32_t)((wn * 64 + nj * 16 + rowB) * 80 +
                                          (ks * 16 + colB) * 2);
                ldm4(bh[nj], s0 + OBH + off);
                ldm4(bl[nj], s0 + OBL + off);
            }
#pragma unroll
            for (int mi = 0; mi < 2; mi++)
#pragma unroll
                for (int nj = 0; nj < 4; nj++)
#pragma unroll
                    for (int sub = 0; sub < 2; sub++) {
                        float* d = acc[mi][nj * 2 + sub];
                        mma16816(d, ah[mi], &bh[nj][sub * 2]);
                        mma16816(d, al[mi], &bh[nj][sub * 2]);
                        mma16816(d, ah[mi], &bl[nj][sub * 2]);
                    }
        }
        __syncthreads();
    }

    // epilogue: direct stores (thread holds rows r, r+8; 2 consecutive cols)
#pragma unroll
    for (int mi = 0; mi < 2; mi++) {
        int r0 = m0 + wm * 32 + mi * 16 + (lane >> 2);
#pragma unroll
        for (int nj = 0; nj < 8; nj++) {
            int c0 = n0 + wn * 64 + nj * 8 + (lane & 3) * 2;
            float* d = acc[mi][nj];
            *reinterpret_cast<float2*>(&Cb[(size_t)r0 * ldc + c0]) =
                make_float2(d[0], d[1]);
            *reinterpret_cast<float2*>(&Cb[(size_t)(r0 + 8) * ldc + c0]) =
                make_float2(d[2], d[3]);
        }
    }
}

// ---------------- helpers: bf16 split ----------------
__device__ __forceinline__ void split_w(float v, bf16* oh, bf16* ol, size_t i) {
    bf16 h = __float2bfloat16(v);
    oh[i] = h;
    ol[i] = __float2bfloat16(v - __bfloat162float(h));
}

// ---------------- layernorm(512) with fused hi/lo split output ----------------
__global__ void layernorm512_split(const float* __restrict__ x, const float* __restrict__ g,
                                   const float* __restrict__ beta,
                                   bf16* __restrict__ oh, bf16* __restrict__ ol) {
    int row = blockIdx.x;
    const float* xr = x + (size_t)row * Dd;
    int tid = threadIdx.x;  // 128
    float v[4];
    float s = 0.f;
#pragma unroll
    for (int i = 0; i < 4; i++) { v[i] = xr[tid + i * 128]; s += v[i]; }
    __shared__ float red[4];
#pragma unroll
    for (int o = 16; o; o >>= 1) s += __shfl_xor_sync(0xffffffffu, s, o);
    if ((tid & 31) == 0) red[tid >> 5] = s;
    __syncthreads();
    float mu = (red[0] + red[1] + red[2] + red[3]) * (1.f / 512.f);
    float vs = 0.f;
#pragma unroll
    for (int i = 0; i < 4; i++) { float t = v[i] - mu; vs += t * t; }
#pragma unroll
    for (int o = 16; o; o >>= 1) vs += __shfl_xor_sync(0xffffffffu, vs, o);
    __syncthreads();
    if ((tid & 31) == 0) red[tid >> 5] = vs;
    __syncthreads();
    float var = (red[0] + red[1] + red[2] + red[3]) * (1.f / 512.f);
    float rstd = rsqrtf(var + 1e-5f);
#pragma unroll
    for (int i = 0; i < 4; i++) {
        int c = tid + i * 128;
        float o = (v[i] - mu) * rstd * g[c] + beta[c];
        split_w(o, oh, ol, (size_t)row * Dd + c);
    }
}

// ---------------- edge dot: d[h,e,p] = edge_attr[e,:] . edge_vec[h,p,:] ----------------
__global__ void edge_d_kernel(const float* __restrict__ edge_attr,
                              const float* __restrict__ edge_vec,
                              float* __restrict__ dout) {
    __shared__ float ea[4][EDd];
    int e0 = blockIdx.x * 4;
    int tid = threadIdx.x;
    for (int i = tid; i < 4 * EDd; i += 128)
        ea[i >> 6][i & 63] = edge_attr[(size_t)e0 * EDd + i];
    __syncthreads();
    int el = tid >> 5;
    int hp = tid & 31;
    const float* ev = edge_vec + hp * EDd;
    float s = 0.f;
#pragma unroll
    for (int f = 0; f < EDd; f++) s += ea[el][f] * ev[f];
    int h = hp >> 2, p = hp & 3;
    dout[((size_t)h * Ee + (e0 + el)) * Pp + p] = s;
}

// ---------------- fused bias(b) + path-bias(c) + softmax -> bf16 hi/lo ----------------
__global__ void bias_c_softmax(const float* __restrict__ S, const float* __restrict__ b,
                               const int* __restrict__ path_idx,
                               const int* __restrict__ path_len,
                               const float* __restrict__ dmat,
                               bf16* __restrict__ Sh, bf16* __restrict__ Sl) {
    int h = blockIdx.x;
    int row = blockIdx.y;
    const float* r = S + ((size_t)h * Nn + row) * Nn;
    const float* br = b + (size_t)row * Nn;
    const int* plr = path_len + (size_t)row * Nn;
    const int* pir = path_idx + (size_t)row * Nn * Pp;
    const float* dh = dmat + (size_t)h * Ee * Pp;
    int tid = threadIdx.x;  // 256
    float v[8];
    float m = -1e30f;
#pragma unroll
    for (int i = 0; i < 8; i++) {
        int col = tid + i * 256;
        int pl = plr[col];
        float c = 0.f;
        if (pl > 0) {
            const int4 pi = *reinterpret_cast<const int4*>(pir + (size_t)col * 4);
            float s = dh[(size_t)pi.x * 4 + 0];
            if (1 < pl) s += dh[(size_t)pi.y * 4 + 1];
            if (2 < pl) s += dh[(size_t)pi.z * 4 + 2];
            if (3 < pl) s += dh[(size_t)pi.w * 4 + 3];
            c = s / (float)pl;
        }
        v[i] = r[col] + br[col] + c;
        m = fmaxf(m, v[i]);
    }
    __shared__ float red[8];
#pragma unroll
    for (int o = 16; o; o >>= 1) m = fmaxf(m, __shfl_xor_sync(0xffffffffu, m, o));
    if ((tid & 31) == 0) red[tid >> 5] = m;
    __syncthreads();
    m = red[0];
#pragma unroll
    for (int i = 1; i < 8; i++) m = fmaxf(m, red[i]);
    float s = 0.f;
#pragma unroll
    for (int i = 0; i < 8; i++) { v[i] = __expf(v[i] - m); s += v[i]; }
#pragma unroll
    for (int o = 16; o; o >>= 1) s += __shfl_xor_sync(0xffffffffu, s, o);
    __syncthreads();
    if ((tid & 31) == 0) red[tid >> 5] = s;
    __syncthreads();
    s = red[0];
#pragma unroll
    for (int i = 1; i < 8; i++) s += red[i];
    float inv = 1.f / s;
    size_t base = ((size_t)h * Nn + row) * Nn;
#pragma unroll
    for (int i = 0; i < 8; i++) {
        float p = v[i] * inv;
        split_w(p, Sh, Sl, base + tid + i * 256);
    }
}

// ---------------- split with optional per-col bias and scale ----------------
__global__ void split_bias_scale(const float* __restrict__ in, const float* __restrict__ bias,
                                 bf16* __restrict__ oh, bf16* __restrict__ ol,
                                 float scale, int colMask, long sIn, long sBias) {
    size_t z = blockIdx.y;
    size_t i = (size_t)blockIdx.x * 256 + threadIdx.x;
    float v = in[z * sIn + i];
    if (bias) v += bias[z * sBias + (i & colMask)];
    v *= scale;
    split_w(v, oh, ol, z * sIn + i);
}

// ---------------- gelu(in + b1) -> hi/lo ----------------
__global__ void gelu_split(const float* __restrict__ in, const float* __restrict__ b1,
                           bf16* __restrict__ oh, bf16* __restrict__ ol) {
    size_t i = (size_t)blockIdx.x * 256 + threadIdx.x;
    float v = in[i] + b1[i & (Ff - 1)];
    v = 0.5f * v * (1.0f + erff(v * 0.70710678118654752f));
    split_w(v, oh, ol, i);
}

// ---------------- out = Cin + bias + resid ----------------
__global__ void bias_resid(float* __restrict__ out, const float* __restrict__ Cin,
                           const float* __restrict__ bias, const float* __restrict__ resid,
                           int mask) {
    size_t i = (size_t)blockIdx.x * 256 + threadIdx.x;
    out[i] = Cin[i] + bias[i & mask] + resid[i];
}

// ---------------- transpose (+optional col bias) + split: [b][R][C] -> [b][C][R] ----------------
__global__ void transpose_split(const float* __restrict__ in, const float* __restrict__ bias,
                                bf16* __restrict__ oh, bf16* __restrict__ ol, int R, int C) {
    __shared__ float t[32][33];
    int bz = blockIdx.z;
    const float* inb = in + (size_t)bz * R * C;
    size_t oz = (size_t)bz * R * C;
    int c0 = blockIdx.x * 32, r0 = blockIdx.y * 32;
    int tx = threadIdx.x, ty = threadIdx.y;  // (32, 8)
#pragma unroll
    for (int k = 0; k < 4; k++) {
        int r = r0 + ty + k * 8;
        float v = inb[(size_t)r * C + c0 + tx];
        if (bias) v += bias[(size_t)bz * C + c0 + tx];
        t[ty + k * 8][tx] = v;
    }
    __syncthreads();
#pragma unroll
    for (int k = 0; k < 4; k++) {
        int c = c0 + ty + k * 8;
        split_w(t[tx][ty + k * 8], oh, ol, oz + (size_t)c * R + r0 + tx);
    }
}

// ---------------- host ----------------
#define GETSYM(var, sym) cudaGetSymbolAddress((void**)&var, sym)

extern "C" void kernel_launch(void* const* d_in, const int* in_sizes, int n_in,
                              void* d_out, int out_size) {
    const float* x         = (const float*)d_in[0];
    const float* edge_attr = (const float*)d_in[1];
    const float* b         = (const float*)d_in[2];
    const int*   path_idx  = (const int*)d_in[3];
    const int*   path_len  = (const int*)d_in[4];
    const float* Wq        = (const float*)d_in[5];
    const float* bq        = (const float*)d_in[6];
    const float* Wk        = (const float*)d_in[7];
    const float* bk        = (const float*)d_in[8];
    const float* Wv        = (const float*)d_in[9];
    const float* bv        = (const float*)d_in[10];
    const float* edge_vec  = (const float*)d_in[11];
    const float* Wo        = (const float*)d_in[12];
    const float* bo        = (const float*)d_in[13];
    const float* ln1_g     = (const float*)d_in[14];
    const float* ln1_b     = (const float*)d_in[15];
    const float* ln2_g     = (const float*)d_in[16];
    const float* ln2_b     = (const float*)d_in[17];
    const float* W1        = (const float*)d_in[18];
    const float* b1        = (const float*)d_in[19];
    const float* W2        = (const float*)d_in[20];
    const float* b2        = (const float*)d_in[21];
    float* out = (float*)d_out;

    float *Qf, *Kf, *Vf, *Sf, *mhf, *x1f, *dmat;
    GETSYM(Qf, g_Q); GETSYM(Kf, g_K); GETSYM(Vf, g_V); GETSYM(Sf, g_S);
    GETSYM(mhf, g_mh); GETSYM(x1f, g_x1); GETSYM(dmat, g_dmat);
    bf16 *xh, *xl, *Qh, *Ql, *Kh, *Kl, *Vth, *Vtl, *Sh, *Sl, *mhh, *mhl;
    bf16 *h2h, *h2l, *ffh, *ffl;
    bf16 *Wqh, *Wql, *Wkh, *Wkl, *Wvh, *Wvl, *Woh, *Wol, *W1h, *W1l, *W2h, *W2l;
    GETSYM(xh, g_xh); GETSYM(xl, g_xl);
    GETSYM(Qh, g_Qh); GETSYM(Ql, g_Ql); GETSYM(Kh, g_Kh); GETSYM(Kl, g_Kl);
    GETSYM(Vth, g_Vth); GETSYM(Vtl, g_Vtl);
    GETSYM(Sh, g_Sh); GETSYM(Sl, g_Sl);
    GETSYM(mhh, g_mhh); GETSYM(mhl, g_mhl);
    GETSYM(h2h, g_h2h); GETSYM(h2l, g_h2l);
    GETSYM(ffh, g_ffh); GETSYM(ffl, g_ffl);
    GETSYM(Wqh, g_Wqh); GETSYM(Wql, g_Wql);
    GETSYM(Wkh, g_Wkh); GETSYM(Wkl, g_Wkl);
    GETSYM(Wvh, g_Wvh); GETSYM(Wvl, g_Wvl);
    GETSYM(Woh, g_Woh); GETSYM(Wol, g_Wol);
    GETSYM(W1h, g_W1h); GETSYM(W1l, g_W1l);
    GETSYM(W2h, g_W2h); GETSYM(W2l, g_W2l);

    cudaFuncSetAttribute(mma_gemm, cudaFuncAttributeMaxDynamicSharedMemorySize, SMEM_GEMM);

    const float scale = 1.0f / sqrtf((float)Dd);
    dim3 tb32(32, 8);

    // weight prep: transpose + split (K-major B operands)
    transpose_split<<<dim3(16, 16, Hh), tb32>>>(Wq, nullptr, Wqh, Wql, Dd, Dd);
    transpose_split<<<dim3(16, 16, Hh), tb32>>>(Wk, nullptr, Wkh, Wkl, Dd, Dd);
    transpose_split<<<dim3(16, 16, Hh), tb32>>>(Wv, nullptr, Wvh, Wvl, Dd, Dd);
    transpose_split<<<dim3(16, 128, 1), tb32>>>(Wo, nullptr, Woh, Wol, Hh * Dd, Dd);
    transpose_split<<<dim3(64, 16, 1), tb32>>>(W1, nullptr, W1h, W1l, Dd, Ff);
    transpose_split<<<dim3(16, 64, 1), tb32>>>(W2, nullptr, W2h, W2l, Ff, Dd);

    // LN1 -> xln hi/lo ; edge dots
    layernorm512_split<<<Nn, 128>>>(x, ln1_g, ln1_b, xh, xl);
    edge_d_kernel<<<Ee / 4, 128>>>(edge_attr, edge_vec, dmat);

    // QKV projections (batched over heads)
    mma_gemm<<<dim3(4, 16, Hh), 256, SMEM_GEMM>>>(xh, xl, Wqh, Wql, Qf, Dd, Dd, Dd, Dd,
                                                  0, (long)Dd * Dd, (long)Nn * Dd);
    mma_gemm<<<dim3(4, 16, Hh), 256, SMEM_GEMM>>>(xh, xl, Wkh, Wkl, Kf, Dd, Dd, Dd, Dd,
                                                  0, (long)Dd * Dd, (long)Nn * Dd);
    mma_gemm<<<dim3(4, 16, Hh), 256, SMEM_GEMM>>>(xh, xl, Wvh, Wvl, Vf, Dd, Dd, Dd, Dd,
                                                  0, (long)Dd * Dd, (long)Nn * Dd);

    // bias (+scale into Q) + split; V: bias + transpose + split
    split_bias_scale<<<dim3((Nn * Dd) / 256, Hh), 256>>>(Qf, bq, Qh, Ql, scale, Dd - 1,
                                                         (long)Nn * Dd, Dd);
    split_bias_scale<<<dim3((Nn * Dd) / 256, Hh), 256>>>(Kf, bk, Kh, Kl, 1.0f, Dd - 1,
                                                         (long)Nn * Dd, Dd);
    transpose_split<<<dim3(16, 64, Hh), tb32>>>(Vf, bv, Vth, Vtl, Nn, Dd);

    // scores S[h] = (Q/sqrtD) @ K^T
    mma_gemm<<<dim3(16, 16, Hh), 256, SMEM_GEMM>>>(Qh, Ql, Kh, Kl, Sf, Dd, Dd, Dd, Nn,
                                                   (long)Nn * Dd, (long)Nn * Dd,
                                                   (long)Nn * Nn);

    // + b + path bias, softmax -> bf16 hi/lo
    bias_c_softmax<<<dim3(Hh, Nn), 256>>>(Sf, b, path_idx, path_len, dmat, Sh, Sl);

    // mh[:, h*D:(h+1)*D] = attn @ V  (B = V^T, K-major over seq)
    mma_gemm<<<dim3(4, 16, Hh), 256, SMEM_GEMM>>>(Sh, Sl, Vth, Vtl, mhf, Nn, Nn, Nn,
                                                  Hh * Dd, (long)Nn * Nn, (long)Dd * Nn,
                                                  (long)Dd);

    // output projection: tmp = mh @ Wo ; x1 = tmp + bo + x
    split_bias_scale<<<dim3((Nn * Hh * Dd) / 256, 1), 256>>>(mhf, nullptr, mhh, mhl, 1.0f,
                                                             0, 0, 0);
    mma_gemm<<<dim3(4, 16, 1), 256, SMEM_GEMM>>>(mhh, mhl, Woh, Wol, Qf, Hh * Dd,
                                                 Hh * Dd, Hh * Dd, Dd, 0, 0, 0);
    bias_resid<<<(Nn * Dd) / 256, 256>>>(x1f, Qf, bo, x, Dd - 1);

    // LN2 -> h2 hi/lo
    layernorm512_split<<<Nn, 128>>>(x1f, ln2_g, ln2_b, h2h, h2l);

    // FF1: tmp = h2 @ W1 ; ff = gelu(tmp + b1)
    mma_gemm<<<dim3(16, 16, 1), 256, SMEM_GEMM>>>(h2h, h2l, W1h, W1l, Sf, Dd, Dd, Dd, Ff,
                                                  0, 0, 0);
    gelu_split<<<((long)Nn * Ff) / 256, 256>>>(Sf, b1, ffh, ffl);

    // FF2: tmp = ff @ W2 ; out = tmp + b2 + x1
    mma_gemm<<<dim3(4, 16, 1), 256, SMEM_GEMM>>>(ffh, ffl, W2h, W2l, Qf, Ff, Ff, Ff, Dd,
                                                 0, 0, 0);
    bias_resid<<<(Nn * Dd) / 256, 256>>>(out, Qf, b2, x1f, Dd - 1);
}

// round 5
// speedup vs baseline: 3.7417x; 1.2185x over previous
#include <cuda_runtime.h>
#include <cuda_fp16.h>
#include <math.h>
#include <stdint.h>

#define Nn 2048
#define Dd 512
#define Hh 8
#define Ff 2048
#define EDd 64
#define Pp 4
#define Ee 32768

typedef __half h16;

// ---------------- static scratch (no allocations allowed) ----------------
__device__ float g_Sf[(size_t)Hh * Nn * Nn];      // 128 MB scores
__device__ float g_x1[Nn * Dd];
__device__ float g_dmat[Hh * Ee * Pp];
__device__ float g_bqkv[24 * Dd];

__device__ h16 g_xh[Nn * Dd], g_xl[Nn * Dd];
__device__ h16 g_QKVh[24 * Nn * Dd], g_QKVl[24 * Nn * Dd];   // Q:0-7 K:8-15 V:16-23
__device__ h16 g_Vth[(size_t)Hh * Dd * Nn];
__device__ h16 g_Sh[(size_t)Hh * Nn * Nn], g_Sl[(size_t)Hh * Nn * Nn];
__device__ h16 g_mhh[(size_t)Nn * Hh * Dd], g_mhl[(size_t)Nn * Hh * Dd];
__device__ h16 g_h2h[Nn * Dd], g_h2l[Nn * Dd];
__device__ h16 g_ffh[Nn * Ff], g_ffl[Nn * Ff];
__device__ h16 g_Wh[24 * Dd * Dd];                            // QKV weights, hi only
__device__ h16 g_Woh[Dd * Hh * Dd], g_Wol[Dd * Hh * Dd];
__device__ h16 g_W1h[Ff * Dd], g_W1l[Ff * Dd];
__device__ h16 g_W2h[Dd * Ff], g_W2l[Dd * Ff];

// ---------------- low-level helpers ----------------
__device__ __forceinline__ uint32_t smem_u32(const void* p) {
    uint32_t a;
    asm("{ .reg .u64 t; cvta.to.shared.u64 t, %1; cvt.u32.u64 %0, t; }" : "=r"(a) : "l"(p));
    return a;
}
__device__ __forceinline__ void ldm4(uint32_t* r, uint32_t addr) {
    asm volatile("ldmatrix.sync.aligned.m8n8.x4.shared.b16 {%0,%1,%2,%3}, [%4];"
                 : "=r"(r[0]), "=r"(r[1]), "=r"(r[2]), "=r"(r[3]) : "r"(addr));
}
__device__ __forceinline__ void mma16816(float* d, const uint32_t* a, const uint32_t* b) {
    asm volatile(
        "mma.sync.aligned.m16n8k16.row.col.f32.f16.f16.f32 "
        "{%0,%1,%2,%3}, {%4,%5,%6,%7}, {%8,%9}, {%0,%1,%2,%3};"
        : "+f"(d[0]), "+f"(d[1]), "+f"(d[2]), "+f"(d[3])
        : "r"(a[0]), "r"(a[1]), "r"(a[2]), "r"(a[3]), "r"(b[0]), "r"(b[1]));
}
__device__ __forceinline__ void cp16(uint32_t sdst, const void* gsrc) {
    asm volatile("cp.async.cg.shared.global [%0], [%1], 16;" :: "r"(sdst), "l"(gsrc));
}
#define CP_COMMIT() asm volatile("cp.async.commit_group;" ::: "memory")
#define CP_WAIT(n)  asm volatile("cp.async.wait_group %0;" :: "n"(n) : "memory")

// one 128x32 fp16 tile (row-major, leading dim ld) into 80B-pitched smem
__device__ __forceinline__ void cp_tile(uint32_t sdst, const h16* __restrict__ src,
                                        int ld, int row0, int k0, int tid) {
#pragma unroll
    for (int it = 0; it < 2; it++) {
        int idx = tid + it * 256;
        int r = idx >> 2, c = idx & 3;
        cp16(sdst + r * 80 + c * 16, src + (size_t)(row0 + r) * ld + k0 + c * 8);
    }
}

__device__ __forceinline__ void split_h(float v, h16* oh, h16* ol, size_t i) {
    h16 h = __float2half_rn(v);
    oh[i] = h;
    ol[i] = __float2half_rn(v - __half2float(h));
}

// ---------------- split-fp16 mma.sync GEMM: acc[M,N] = sum_k A[m,k]*B[n,k] ----------------
// PASSES=2: Ah*Bh + Al*Bh (err ~2^-12). PASSES=3: + Ah*Bl (err ~2^-24).
// EPI: 0 = fp32 C; 1 = (acc+bias) split -> Oh/Ol; 2 = gelu(acc+bias) split; 3 = acc+bias+resid fp32
template <int PASSES, int EPI>
__global__ void __launch_bounds__(256, 1)
gemm_h(const h16* __restrict__ Ah_, const h16* __restrict__ Al_,
       const h16* __restrict__ Bh_, const h16* __restrict__ Bl_,
       float* __restrict__ C, h16* __restrict__ Oh, h16* __restrict__ Ol,
       const float* __restrict__ bias, const float* __restrict__ resid,
       int K, int lda, int ldb, int ldc,
       long sA, long sB, long sC, long sBias) {
    constexpr int NT = (PASSES == 3) ? 4 : 3;
    constexpr int STG = NT * 10240;
    constexpr int OAH = 0, OAL = 10240, OBH = 20480, OBL = 30720;
    extern __shared__ char smem[];
    const int tid = threadIdx.x;
    const int lane = tid & 31;
    const int wid = tid >> 5;
    const int wm = wid & 3;
    const int wn = wid >> 2;
    const int bz = blockIdx.z;
    const h16* Ahb = Ah_ + (size_t)bz * sA;
    const h16* Alb = Al_ + (size_t)bz * sA;
    const h16* Bhb = Bh_ + (size_t)bz * sB;
    const h16* Blb = (PASSES == 3) ? Bl_ + (size_t)bz * sB : nullptr;
    const int m0 = blockIdx.y * 128;
    const int n0 = blockIdx.x * 128;
    const uint32_t sb = smem_u32(smem);

    float acc[2][8][4];
#pragma unroll
    for (int i = 0; i < 2; i++)
#pragma unroll
        for (int j = 0; j < 8; j++)
#pragma unroll
            for (int t = 0; t < 4; t++) acc[i][j][t] = 0.f;

    const int rowA = (lane & 15);
    const int colA = (lane >> 4) * 8;
    const int rowB = (lane & 7) + ((lane >> 4) & 1) * 8;
    const int colB = ((lane >> 3) & 1) * 8;

    const int nk = K >> 5;

    {
        cp_tile(sb + OAH, Ahb, lda, m0, 0, tid);
        cp_tile(sb + OAL, Alb, lda, m0, 0, tid);
        cp_tile(sb + OBH, Bhb, ldb, n0, 0, tid);
        if (PASSES == 3) cp_tile(sb + OBL, Blb, ldb, n0, 0, tid);
        CP_COMMIT();
    }

    for (int kt = 0; kt < nk; kt++) {
        if (kt + 1 < nk) {
            uint32_t s1 = sb + ((kt + 1) & 1) * STG;
            int k0 = (kt + 1) << 5;
            cp_tile(s1 + OAH, Ahb, lda, m0, k0, tid);
            cp_tile(s1 + OAL, Alb, lda, m0, k0, tid);
            cp_tile(s1 + OBH, Bhb, ldb, n0, k0, tid);
            if (PASSES == 3) cp_tile(s1 + OBL, Blb, ldb, n0, k0, tid);
            CP_COMMIT();
            CP_WAIT(1);
        } else {
            CP_WAIT(0);
        }
        __syncthreads();

        uint32_t s0 = sb + (kt & 1) * STG;
#pragma unroll
        for (int ks = 0; ks < 2; ks++) {
            uint32_t ah[2][4], al[2][4], bh[4][4], bl[4][4];
#pragma unroll
            for (int mi = 0; mi < 2; mi++) {
                uint32_t off = (uint32_t)((wm * 32 + mi * 16 + rowA) * 80 +
                                          (ks * 16 + colA) * 2);
                ldm4(ah[mi], s0 + OAH + off);
                ldm4(al[mi], s0 + OAL + off);
            }
#pragma unroll
            for (int nj = 0; nj < 4; nj++) {
                uint32_t off = (uint32_t)((wn * 64 + nj * 16 + rowB) * 80 +
                                          (ks * 16 + colB) * 2);
                ldm4(bh[nj], s0 + OBH + off);
                if (PASSES == 3) ldm4(bl[nj], s0 + OBL + off);
            }
#pragma unroll
            for (int mi = 0; mi < 2; mi++)
#pragma unroll
                for (int nj = 0; nj < 4; nj++)
#pragma unroll
                    for (int sub = 0; sub < 2; sub++) {
                        float* d = acc[mi][nj * 2 + sub];
                        mma16816(d, ah[mi], &bh[nj][sub * 2]);
                        mma16816(d, al[mi], &bh[nj][sub * 2]);
                        if (PASSES == 3) mma16816(d, ah[mi], &bl[nj][sub * 2]);
                    }
        }
        __syncthreads();
    }

    // epilogue
#pragma unroll
    for (int mi = 0; mi < 2; mi++) {
        int rbase = m0 + wm * 32 + mi * 16 + (lane >> 2);
#pragma unroll
        for (int nj = 0; nj < 8; nj++) {
            int c0 = n0 + wn * 64 + nj * 8 + (lane & 3) * 2;
            float* d = acc[mi][nj];
#pragma unroll
            for (int half_row = 0; half_row < 2; half_row++) {
                int r = rbase + half_row * 8;
                float v0 = d[half_row * 2 + 0];
                float v1 = d[half_row * 2 + 1];
                if (EPI == 0) {
                    *reinterpret_cast<float2*>(&C[(size_t)bz * sC + (size_t)r * ldc + c0]) =
                        make_float2(v0, v1);
                } else if (EPI == 3) {
                    v0 += bias[c0] + resid[(size_t)r * ldc + c0];
                    v1 += bias[c0 + 1] + resid[(size_t)r * ldc + c0 + 1];
                    *reinterpret_cast<float2*>(&C[(size_t)r * ldc + c0]) =
                        make_float2(v0, v1);
                } else {
                    if (bias) {
                        v0 += bias[(size_t)bz * sBias + c0];
                        v1 += bias[(size_t)bz * sBias + c0 + 1];
                    }
                    if (EPI == 2) {
                        v0 = 0.5f * v0 * (1.0f + erff(v0 * 0.70710678118654752f));
                        v1 = 0.5f * v1 * (1.0f + erff(v1 * 0.70710678118654752f));
                    }
                    h16 h0 = __float2half_rn(v0), h1 = __float2half_rn(v1);
                    size_t o = (size_t)bz * sC + (size_t)r * ldc + c0;
                    *reinterpret_cast<__half2*>(&Oh[o]) = __halves2half2(h0, h1);
                    *reinterpret_cast<__half2*>(&Ol[o]) = __halves2half2(
                        __float2half_rn(v0 - __half2float(h0)),
                        __float2half_rn(v1 - __half2float(h1)));
                }
            }
        }
    }
}

// ---------------- weight prep: fp32 [R][C] -> fp16 [C][R] hi (+opt lo), scaled ----------------
__global__ void transpose_w(const float* __restrict__ in, h16* __restrict__ oh,
                            h16* __restrict__ ol, int R, int C, float scale) {
    __shared__ float t[32][33];
    int bz = blockIdx.z;
    const float* inb = in + (size_t)bz * R * C;
    size_t oz = (size_t)bz * R * C;
    int c0 = blockIdx.x * 32, r0 = blockIdx.y * 32;
    int tx = threadIdx.x, ty = threadIdx.y;  // (32,8)
#pragma unroll
    for (int k = 0; k < 4; k++) {
        int r = r0 + ty + k * 8;
        t[ty + k * 8][tx] = in[(size_t)bz * R * C + (size_t)r * C + c0 + tx] * scale;
    }
    __syncthreads();
#pragma unroll
    for (int k = 0; k < 4; k++) {
        int c = c0 + ty + k * 8;
        float v = t[tx][ty + k * 8];
        size_t i = oz + (size_t)c * R + r0 + tx;
        h16 h = __float2half_rn(v);
        oh[i] = h;
        if (ol) ol[i] = __float2half_rn(v - __half2float(h));
    }
    (void)inb;
}

// ---------------- V transpose: fp16 [N][D] -> [D][N] per batch ----------------
__global__ void transpose_h(const h16* __restrict__ in, h16* __restrict__ out, int R, int C) {
    __shared__ h16 t[32][33];
    int bz = blockIdx.z;
    const h16* inb = in + (size_t)bz * R * C;
    h16* ob = out + (size_t)bz * R * C;
    int c0 = blockIdx.x * 32, r0 = blockIdx.y * 32;
    int tx = threadIdx.x, ty = threadIdx.y;
#pragma unroll
    for (int k = 0; k < 4; k++) t[ty + k * 8][tx] = inb[(size_t)(r0 + ty + k * 8) * C + c0 + tx];
    __syncthreads();
#pragma unroll
    for (int k = 0; k < 4; k++)
        ob[(size_t)(c0 + ty + k * 8) * R + r0 + tx] = t[tx][ty + k * 8];
}

// ---------------- pack QKV biases (scale folded into Q) ----------------
__global__ void pack_bias(const float* __restrict__ bq, const float* __restrict__ bk,
                          const float* __restrict__ bv, float* __restrict__ o, float s) {
    int i = blockIdx.x * 256 + threadIdx.x;  // 24*512
    int z = i >> 9, c = i & 511;
    float v = (z < 8) ? bq[z * 512 + c] * s
                      : ((z < 16) ? bk[(z - 8) * 512 + c] : bv[(z - 16) * 512 + c]);
    o[i] = v;
}

// ---------------- layernorm(512) -> fp16 hi/lo ----------------
__global__ void layernorm512_split(const float* __restrict__ x, const float* __restrict__ g,
                                   const float* __restrict__ beta,
                                   h16* __restrict__ oh, h16* __restrict__ ol) {
    int row = blockIdx.x;
    const float* xr = x + (size_t)row * Dd;
    int tid = threadIdx.x;  // 128
    float v[4];
    float s = 0.f;
#pragma unroll
    for (int i = 0; i < 4; i++) { v[i] = xr[tid + i * 128]; s += v[i]; }
    __shared__ float red[4];
#pragma unroll
    for (int o = 16; o; o >>= 1) s += __shfl_xor_sync(0xffffffffu, s, o);
    if ((tid & 31) == 0) red[tid >> 5] = s;
    __syncthreads();
    float mu = (red[0] + red[1] + red[2] + red[3]) * (1.f / 512.f);
    float vs = 0.f;
#pragma unroll
    for (int i = 0; i < 4; i++) { float t = v[i] - mu; vs += t * t; }
#pragma unroll
    for (int o = 16; o; o >>= 1) vs += __shfl_xor_sync(0xffffffffu, vs, o);
    __syncthreads();
    if ((tid & 31) == 0) red[tid >> 5] = vs;
    __syncthreads();
    float var = (red[0] + red[1] + red[2] + red[3]) * (1.f / 512.f);
    float rstd = rsqrtf(var + 1e-5f);
#pragma unroll
    for (int i = 0; i < 4; i++) {
        int c = tid + i * 128;
        float o = (v[i] - mu) * rstd * g[c] + beta[c];
        split_h(o, oh, ol, (size_t)row * Dd + c);
    }
}

// ---------------- edge dot ----------------
__global__ void edge_d_kernel(const float* __restrict__ edge_attr,
                              const float* __restrict__ edge_vec,
                              float* __restrict__ dout) {
    __shared__ float ea[4][EDd];
    int e0 = blockIdx.x * 4;
    int tid = threadIdx.x;
    for (int i = tid; i < 4 * EDd; i += 128)
        ea[i >> 6][i & 63] = edge_attr[(size_t)e0 * EDd + i];
    __syncthreads();
    int el = tid >> 5;
    int hp = tid & 31;
    const float* ev = edge_vec + hp * EDd;
    float s = 0.f;
#pragma unroll
    for (int f = 0; f < EDd; f++) s += ea[el][f] * ev[f];
    int h = hp >> 2, p = hp & 3;
    dout[((size_t)h * Ee + (e0 + el)) * Pp + p] = s;
}

// ---------------- fused bias(b) + path-bias + softmax -> fp16 hi/lo ----------------
__global__ void bias_c_softmax(const float* __restrict__ S, const float* __restrict__ b,
                               const int* __restrict__ path_idx,
                               const int* __restrict__ path_len,
                               const float* __restrict__ dmat,
                               h16* __restrict__ Sh, h16* __restrict__ Sl) {
    int h = blockIdx.x;
    int row = blockIdx.y;
    const float* r = S + ((size_t)h * Nn + row) * Nn;
    const float* br = b + (size_t)row * Nn;
    const int* plr = path_len + (size_t)row * Nn;
    const int* pir = path_idx + (size_t)row * Nn * Pp;
    const float* dh = dmat + (size_t)h * Ee * Pp;
    int tid = threadIdx.x;  // 256
    float v[8];
    float m = -1e30f;
#pragma unroll
    for (int i = 0; i < 8; i++) {
        int col = tid + i * 256;
        int pl = plr[col];
        float c = 0.f;
        if (pl > 0) {
            const int4 pi = *reinterpret_cast<const int4*>(pir + (size_t)col * 4);
            float s = dh[(size_t)pi.x * 4 + 0];
            if (1 < pl) s += dh[(size_t)pi.y * 4 + 1];
            if (2 < pl) s += dh[(size_t)pi.z * 4 + 2];
            if (3 < pl) s += dh[(size_t)pi.w * 4 + 3];
            c = s / (float)pl;
        }
        v[i] = r[col] + br[col] + c;
        m = fmaxf(m, v[i]);
    }
    __shared__ float red[8];
#pragma unroll
    for (int o = 16; o; o >>= 1) m = fmaxf(m, __shfl_xor_sync(0xffffffffu, m, o));
    if ((tid & 31) == 0) red[tid >> 5] = m;
    __syncthreads();
    m = red[0];
#pragma unroll
    for (int i = 1; i < 8; i++) m = fmaxf(m, red[i]);
    float s = 0.f;
#pragma unroll
    for (int i = 0; i < 8; i++) { v[i] = __expf(v[i] - m); s += v[i]; }
#pragma unroll
    for (int o = 16; o; o >>= 1) s += __shfl_xor_sync(0xffffffffu, s, o);
    __syncthreads();
    if ((tid & 31) == 0) red[tid >> 5] = s;
    __syncthreads();
    s = red[0];
#pragma unroll
    for (int i = 1; i < 8; i++) s += red[i];
    float inv = 1.f / s;
    size_t base = ((size_t)h * Nn + row) * Nn;
#pragma unroll
    for (int i = 0; i < 8; i++) split_h(v[i] * inv, Sh, Sl, base + tid + i * 256);
}

// ---------------- host ----------------
#define GETSYM(var, sym) cudaGetSymbolAddress((void**)&var, sym)

extern "C" void kernel_launch(void* const* d_in, const int* in_sizes, int n_in,
                              void* d_out, int out_size) {
    const float* x         = (const float*)d_in[0];
    const float* edge_attr = (const float*)d_in[1];
    const float* b         = (const float*)d_in[2];
    const int*   path_idx  = (const int*)d_in[3];
    const int*   path_len  = (const int*)d_in[4];
    const float* Wq        = (const float*)d_in[5];
    const float* bq        = (const float*)d_in[6];
    const float* Wk        = (const float*)d_in[7];
    const float* bk        = (const float*)d_in[8];
    const float* Wv        = (const float*)d_in[9];
    const float* bv        = (const float*)d_in[10];
    const float* edge_vec  = (const float*)d_in[11];
    const float* Wo        = (const float*)d_in[12];
    const float* bo        = (const float*)d_in[13];
    const float* ln1_g     = (const float*)d_in[14];
    const float* ln1_b     = (const float*)d_in[15];
    const float* ln2_g     = (const float*)d_in[16];
    const float* ln2_b     = (const float*)d_in[17];
    const float* W1        = (const float*)d_in[18];
    const float* b1        = (const float*)d_in[19];
    const float* W2        = (const float*)d_in[20];
    const float* b2        = (const float*)d_in[21];
    float* out = (float*)d_out;

    float *Sf, *x1f, *dmat, *bqkv;
    GETSYM(Sf, g_Sf); GETSYM(x1f, g_x1); GETSYM(dmat, g_dmat); GETSYM(bqkv, g_bqkv);
    h16 *xh, *xl, *QKVh, *QKVl, *Vth, *Sh, *Sl, *mhh, *mhl, *h2h, *h2l, *ffh, *ffl;
    h16 *Wh, *Woh, *Wol, *W1h, *W1l, *W2h, *W2l;
    GETSYM(xh, g_xh); GETSYM(xl, g_xl);
    GETSYM(QKVh, g_QKVh); GETSYM(QKVl, g_QKVl);
    GETSYM(Vth, g_Vth);
    GETSYM(Sh, g_Sh); GETSYM(Sl, g_Sl);
    GETSYM(mhh, g_mhh); GETSYM(mhl, g_mhl);
    GETSYM(h2h, g_h2h); GETSYM(h2l, g_h2l);
    GETSYM(ffh, g_ffh); GETSYM(ffl, g_ffl);
    GETSYM(Wh, g_Wh);
    GETSYM(Woh, g_Woh); GETSYM(Wol, g_Wol);
    GETSYM(W1h, g_W1h); GETSYM(W1l, g_W1l);
    GETSYM(W2h, g_W2h); GETSYM(W2l, g_W2l);

    static bool attr_done = false;
    if (!attr_done) {
        cudaFuncSetAttribute(gemm_h<2, 0>, cudaFuncAttributeMaxDynamicSharedMemorySize, 61440);
        cudaFuncSetAttribute(gemm_h<2, 1>, cudaFuncAttributeMaxDynamicSharedMemorySize, 61440);
        cudaFuncSetAttribute(gemm_h<3, 2>, cudaFuncAttributeMaxDynamicSharedMemorySize, 81920);
        cudaFuncSetAttribute(gemm_h<3, 3>, cudaFuncAttributeMaxDynamicSharedMemorySize, 81920);
        attr_done = true;
    }

    const float scale = 1.0f / sqrtf((float)Dd);
    dim3 tb32(32, 8);
    const long ND = (long)Nn * Dd;
    const long NN = (long)Nn * Nn;

    // weight prep (transpose to K-major fp16)
    transpose_w<<<dim3(16, 16, Hh), tb32>>>(Wq, Wh, nullptr, Dd, Dd, scale);
    transpose_w<<<dim3(16, 16, Hh), tb32>>>(Wk, Wh + 8 * Dd * Dd, nullptr, Dd, Dd, 1.f);
    transpose_w<<<dim3(16, 16, Hh), tb32>>>(Wv, Wh + 16 * Dd * Dd, nullptr, Dd, Dd, 1.f);
    transpose_w<<<dim3(16, 128, 1), tb32>>>(Wo, Woh, Wol, Hh * Dd, Dd, 1.f);
    transpose_w<<<dim3(64, 16, 1), tb32>>>(W1, W1h, W1l, Dd, Ff, 1.f);
    transpose_w<<<dim3(16, 64, 1), tb32>>>(W2, W2h, W2l, Ff, Dd, 1.f);
    pack_bias<<<48, 256>>>(bq, bk, bv, bqkv, scale);

    // LN1, edge dots
    layernorm512_split<<<Nn, 128>>>(x, ln1_g, ln1_b, xh, xl);
    edge_d_kernel<<<Ee / 4, 128>>>(edge_attr, edge_vec, dmat);

    // QKV: one batched GEMM (24 batches), epilogue = +bias, split fp16
    gemm_h<2, 1><<<dim3(4, 16, 24), 256, 61440>>>(
        xh, xl, Wh, nullptr, nullptr, QKVh, QKVl, bqkv, nullptr,
        Dd, Dd, Dd, Dd, 0, (long)Dd * Dd, ND, Dd);

    // V transpose (hi only) -> [H][D][N]
    transpose_h<<<dim3(16, 64, Hh), tb32>>>(QKVh + 16 * ND, Vth, Nn, Dd);

    // scores: S[h] = Qs @ K^T (fp32 out)
    gemm_h<2, 0><<<dim3(16, 16, Hh), 256, 61440>>>(
        QKVh, QKVl, QKVh + 8 * ND, nullptr, Sf, nullptr, nullptr, nullptr, nullptr,
        Dd, Dd, Dd, Nn, ND, ND, NN, 0);

    // spatial + path bias, softmax -> fp16 hi/lo
    bias_c_softmax<<<dim3(Hh, Nn), 256>>>(Sf, b, path_idx, path_len, dmat, Sh, Sl);

    // attn @ V -> mh (split fp16 directly, col-block per head)
    gemm_h<2, 1><<<dim3(4, 16, Hh), 256, 61440>>>(
        Sh, Sl, Vth, nullptr, nullptr, mhh, mhl, nullptr, nullptr,
        Nn, Nn, Nn, Hh * Dd, NN, (long)Dd * Nn, Dd, 0);

    // x1 = mh @ Wo + bo + x  (3-pass, fused residual)
    gemm_h<3, 3><<<dim3(4, 16, 1), 256, 81920>>>(
        mhh, mhl, Woh, Wol, x1f, nullptr, nullptr, bo, x,
        Hh * Dd, Hh * Dd, Hh * Dd, Dd, 0, 0, 0, 0);

    // LN2
    layernorm512_split<<<Nn, 128>>>(x1f, ln2_g, ln2_b, h2h, h2l);

    // ff = gelu(h2 @ W1 + b1) (3-pass, fused gelu+split)
    gemm_h<3, 2><<<dim3(16, 16, 1), 256, 81920>>>(
        h2h, h2l, W1h, W1l, nullptr, ffh, ffl, b1, nullptr,
        Dd, Dd, Dd, Ff, 0, 0, 0, 0);

    // out = ff @ W2 + b2 + x1 (3-pass, fused residual)
    gemm_h<3, 3><<<dim3(4, 16, 1), 256, 81920>>>(
        ffh, ffl, W2h, W2l, out, nullptr, nullptr, b2, x1f,
        Ff, Ff, Ff, Dd, 0, 0, 0, 0);
}